// round 15
// baseline (speedup 1.0000x reference)
#include <cuda_runtime.h>
#include <cstdint>

#define N2    361
#define NTHR  384
#define TS    512
#define OVF   24
#define NEGV  (-1000000000.0f)
#define I32MIN_V (-2147483647 - 1)
#define GRIDB 592                     // 148 SMs * 4 resident blocks

__global__ __launch_bounds__(NTHR, 4)
void board_kernel(const float* __restrict__ logits,
                  const int* __restrict__ legal,      // bool as int32
                  const int* __restrict__ player,
                  const int* __restrict__ cur_hash,
                  const int* __restrict__ hist,
                  const int* __restrict__ move_count,
                  const int* __restrict__ ZposT,
                  const int* __restrict__ sgi,
                  const int* __restrict__ cap,
                  float* __restrict__ out,
                  int B)
{
    __shared__ int sh_tab[4][TS];     // 4 buffers: pairs alternate {0,1}/{2,3}
    __shared__ int sh_gx[4][8];
    __shared__ int sh_ovf[4][OVF];
    __shared__ int sh_ovfn[4];
    __shared__ int sh_zd[2][N2];      // delta tables: [0]=ze^zb, [1]=ze^zw

    const int t   = threadIdx.x;
    const bool w11 = ((t >> 5) == 11);
    const int l   = t & 31;
    const int g   = gridDim.x;

    for (int i = t; i < N2; i += NTHR) {
        const int ze = ZposT[i];
        sh_zd[0][i] = ze ^ ZposT[N2 + i];
        sh_zd[1][i] = ze ^ ZposT[2 * N2 + i];
    }
    for (int i = t; i < 4 * TS / 4; i += NTHR)
        reinterpret_cast<int4*>(sh_tab)[i] = make_int4(-1, -1, -1, -1);
    if (t < 4) sh_ovfn[t] = 0;
    __syncthreads();

    // prefetch hist/sgi for the first pair
    int hA_c = 0, hB_c = 0, sgA_c = 0, sgB_c = 0;
    {
        const int a0 = blockIdx.x, b0 = a0 + g;
        if (a0 < B) {
            if (t < N2) hA_c = __ldcs(hist + a0 * N2 + t);
            if (w11)    sgA_c = __ldcs(sgi + a0 * 32 + l);
        }
        if (b0 < B) {
            if (t < N2) hB_c = __ldcs(hist + b0 * N2 + t);
            if (w11)    sgB_c = __ldcs(sgi + b0 * 32 + l);
        }
    }

#define PROBE(P, CAND, MC, BI, REP)                                              \
    {                                                                            \
        const unsigned u = (unsigned)(CAND) * 2654435761u;                       \
        REP = (sh_tab[P][u >> 23] == (CAND)) |                                   \
              (sh_tab[P][(u >> 12) & (TS - 1)] == (CAND)) |                      \
              (sh_tab[P][(u ^ (u >> 9)) & (TS - 1)] == (CAND)) |                 \
              ((CAND) == I32MIN_V);                                              \
        int ovn = sh_ovfn[P];                                                    \
        const bool fbk = (ovn > OVF);                                            \
        if (ovn > OVF) ovn = OVF;                                                \
        for (int i2 = 0; i2 < ovn; ++i2) REP |= (sh_ovf[P][i2] == (CAND));       \
        if (fbk && !REP)                                                         \
            for (int q = 0; q < (MC) && !REP; ++q)                               \
                REP = (hist[(BI) * N2 + q] == (CAND));                           \
    }

#define CASFIX(P, KEY, INS)                                                      \
    if (INS) {                                                                   \
        const unsigned u = (unsigned)(KEY) * 2654435761u;                        \
        if (sh_tab[P][u >> 23] != (KEY)) {                                       \
            int prev = atomicCAS(&sh_tab[P][(u >> 12) & (TS - 1)], -1, (KEY));   \
            if (prev != -1 && prev != (KEY)) {                                   \
                prev = atomicCAS(&sh_tab[P][(u ^ (u >> 9)) & (TS - 1)], -1, (KEY)); \
                if (prev != -1 && prev != (KEY)) {                               \
                    const int oi = atomicAdd(&sh_ovfn[P], 1);                    \
                    if (oi < OVF) sh_ovf[P][oi] = (KEY);                         \
                }                                                                \
            }                                                                    \
        }                                                                        \
    }

#define PAIR(PA, PB, WA, BA)                                                     \
    {                                                                            \
        const int bA = (BA);                                                     \
        const int bB = bA + g;                                                   \
        const bool vB = (bB < B);                                                \
        const int plA = player[bA] & 1;                                          \
        const int chA = cur_hash[bA];                                            \
        int mcA = move_count[bA];                                                \
        if (mcA < 0) mcA = 0; if (mcA > N2 - 1) mcA = N2 - 1;                    \
        int plB = 0, chB = 0, mcB = 0;                                           \
        if (vB) {                                                                \
            plB = player[bB] & 1; chB = cur_hash[bB];                            \
            mcB = move_count[bB];                                                \
            if (mcB < 0) mcB = 0; if (mcB > N2 - 1) mcB = N2 - 1;                \
        }                                                                        \
        int4 c4A = make_int4(-1, -1, -1, -1), c4B = make_int4(-1, -1, -1, -1);   \
        float fA = NEGV, fB = NEGV;                                              \
        if (t < N2) {                                                            \
            const int ixA = bA * N2 + t;                                         \
            c4A = __ldcs(reinterpret_cast<const int4*>(cap) + ixA);              \
            const float la = __ldcs(logits + ixA);                               \
            if (__ldcs(legal + ixA)) fA = la;                                    \
            if (vB) {                                                            \
                const int ixB = bB * N2 + t;                                     \
                c4B = __ldcs(reinterpret_cast<const int4*>(cap) + ixB);          \
                const float lb = __ldcs(logits + ixB);                           \
                if (__ldcs(legal + ixB)) fB = lb;                                \
            }                                                                    \
        }                                                                        \
        int hnA = 0, hnB = 0, sgnA = 0, sgnB = 0;                                \
        {                                                                        \
            const int nA = bA + 2 * g, nB = nA + g;                              \
            if (nA < B) {                                                        \
                if (t < N2) hnA = __ldcs(hist + nA * N2 + t);                    \
                if (w11)    sgnA = __ldcs(sgi + nA * 32 + l);                    \
            }                                                                    \
            if (nB < B) {                                                        \
                if (t < N2) hnB = __ldcs(hist + nB * N2 + t);                    \
                if (w11)    sgnB = __ldcs(sgi + nB * 32 + l);                    \
            }                                                                    \
        }                                                                        \
        /* phase 1: group XOR + STS pass-1 inserts */                            \
        if (w11) {                                                               \
            int si = sgA_c; si = si < 0 ? 0 : (si >= N2 ? N2 - 1 : si);          \
            int d = sh_zd[1 - plA][si];                                          \
            d ^= __shfl_xor_sync(0xffffffffu, d, 1);                             \
            d ^= __shfl_xor_sync(0xffffffffu, d, 2);                             \
            if ((l & 3) == 0) sh_gx[PA][l >> 2] = d;                             \
            if (vB) {                                                            \
                int sj = sgB_c; sj = sj < 0 ? 0 : (sj >= N2 ? N2 - 1 : sj);      \
                int e = sh_zd[1 - plB][sj];                                      \
                e ^= __shfl_xor_sync(0xffffffffu, e, 1);                         \
                e ^= __shfl_xor_sync(0xffffffffu, e, 2);                         \
                if ((l & 3) == 0) sh_gx[PB][l >> 2] = e;                         \
            }                                                                    \
        }                                                                        \
        const bool iA = (t < mcA);                                               \
        const bool iB = vB && (t < mcB);                                         \
        const int keyA = hA_c, keyB = hB_c;                                      \
        if (iA) {                                                                \
            const unsigned u = (unsigned)keyA * 2654435761u;                     \
            sh_tab[PA][u >> 23] = keyA;                                          \
        }                                                                        \
        if (iB) {                                                                \
            const unsigned u = (unsigned)keyB * 2654435761u;                     \
            sh_tab[PB][u >> 23] = keyB;                                          \
        }                                                                        \
        __syncthreads();                                                         \
        /* phase 2: CAS-fix this pair + bulk-wipe the other pair's buffers */    \
        CASFIX(PA, keyA, iA)                                                     \
        CASFIX(PB, keyB, iB)                                                     \
        if (t < 256)                                                             \
            reinterpret_cast<int4*>(sh_tab[WA])[t] = make_int4(-1, -1, -1, -1);  \
        if (t == 0) { sh_ovfn[WA] = 0; sh_ovfn[(WA) + 1] = 0; }                  \
        __syncthreads();                                                         \
        /* phase 3: probe + output */                                            \
        if (t < N2) {                                                            \
            int cd = 0;                                                          \
            if (c4A.x >= 0) cd ^= sh_gx[PA][c4A.x & 7];                          \
            if (c4A.y >= 0) cd ^= sh_gx[PA][c4A.y & 7];                          \
            if (c4A.z >= 0) cd ^= sh_gx[PA][c4A.z & 7];                          \
            if (c4A.w >= 0) cd ^= sh_gx[PA][c4A.w & 7];                          \
            const int candA = chA ^ sh_zd[plA][t] ^ cd;                          \
            bool repA;                                                           \
            PROBE(PA, candA, mcA, bA, repA)                                      \
            __stcs(out + bA * N2 + t, repA ? NEGV : fA);                         \
            if (vB) {                                                            \
                int ce = 0;                                                      \
                if (c4B.x >= 0) ce ^= sh_gx[PB][c4B.x & 7];                      \
                if (c4B.y >= 0) ce ^= sh_gx[PB][c4B.y & 7];                      \
                if (c4B.z >= 0) ce ^= sh_gx[PB][c4B.z & 7];                      \
                if (c4B.w >= 0) ce ^= sh_gx[PB][c4B.w & 7];                      \
                const int candB = chB ^ sh_zd[plB][t] ^ ce;                      \
                bool repB;                                                       \
                PROBE(PB, candB, mcB, bB, repB)                                  \
                __stcs(out + bB * N2 + t, repB ? NEGV : fB);                     \
            }                                                                    \
        }                                                                        \
        hA_c = hnA; hB_c = hnB; sgA_c = sgnA; sgB_c = sgnB;                      \
    }

    for (int b = blockIdx.x; b < B; b += 4 * g) {
        PAIR(0, 1, 2, b)                  // uses bufs {0,1}, wipes {2,3}
        const int b2 = b + 2 * g;
        if (b2 < B) {
            PAIR(2, 3, 0, b2)             // uses bufs {2,3}, wipes {0,1}
        }
    }
#undef PAIR
#undef CASFIX
#undef PROBE
}

extern "C" void kernel_launch(void* const* d_in, const int* in_sizes, int n_in,
                              void* d_out, int out_size)
{
    const float* logits = (const float*)d_in[0];
    const int*   legal  = (const int*)d_in[1];
    const int*   player = (const int*)d_in[2];
    const int*   chash  = (const int*)d_in[3];
    const int*   hist   = (const int*)d_in[4];
    const int*   mcnt   = (const int*)d_in[5];
    const int*   zpos   = (const int*)d_in[6];
    const int*   sgi    = (const int*)d_in[7];
    const int*   cap    = (const int*)d_in[10];
    float*       out    = (float*)d_out;

    const int B = in_sizes[2];           // current_player: B elements

    board_kernel<<<GRIDB, NTHR>>>(logits, legal, player, chash, hist, mcnt,
                                  zpos, sgi, cap, out, B);
}

// round 16
// speedup vs baseline: 1.5266x; 1.5266x over previous
#include <cuda_runtime.h>
#include <cstdint>

#define N2    361
#define NTHR  384
#define TS    1024
#define OVF   16
#define NEGV  (-1000000000.0f)
#define I32MIN_V (-2147483647 - 1)
#define GRIDB 740                     // 148 SMs * 5 resident blocks

__global__ __launch_bounds__(NTHR, 5)
void board_kernel(const float* __restrict__ logits,
                  const int* __restrict__ legal,      // bool as int32
                  const int* __restrict__ player,
                  const int* __restrict__ cur_hash,
                  const int* __restrict__ hist,
                  const int* __restrict__ move_count,
                  const int* __restrict__ ZposT,
                  const int* __restrict__ sgi,
                  const int* __restrict__ cap,
                  float* __restrict__ out,
                  int B)
{
    __shared__ int sh_tab[2][TS];     // double-buffered exact table
    __shared__ int sh_gx[2][8];
    __shared__ int sh_ovf[2][OVF];
    __shared__ int sh_ovfn[2];
    __shared__ int sh_zd[2][N2];      // delta tables: [0]=ze^zb, [1]=ze^zw

    const int t = threadIdx.x;
    const bool w11 = ((t >> 5) == 11);
    const int l = t & 31;

    for (int i = t; i < N2; i += NTHR) {
        const int ze = ZposT[i];
        sh_zd[0][i] = ze ^ ZposT[N2 + i];
        sh_zd[1][i] = ze ^ ZposT[2 * N2 + i];
    }
    for (int i = t; i < 2 * TS / 4; i += NTHR)
        reinterpret_cast<int4*>(sh_tab)[i] = make_int4(-1, -1, -1, -1);
    if (t < 2) sh_ovfn[t] = 0;
    __syncthreads();

    // per-buffer clear state (slots written 2 boards ago)
    bool cl_ins0 = false, cl_ins1 = false;
    int  cl0_1 = 0, cl0_2 = 0;
    int  cl1_1 = 0, cl1_2 = 0;

    const int g = gridDim.x;

    // prologue prefetch for first board
    int h_cur = 0, sg_cur = 0;
    {
        const int b0 = blockIdx.x;
        if (b0 < B) {
            if (t < N2) h_cur = __ldcs(hist + b0 * N2 + t);
            if (w11)    sg_cur = __ldcs(sgi + b0 * 32 + l);
        }
    }

#define BODY(P, BCUR, BNXT, CLI, CL1, CL2)                                       \
    {                                                                            \
        const int pl = player[BCUR] & 1;                                         \
        const int ch = cur_hash[BCUR];                                           \
        int mc = move_count[BCUR];                                               \
        if (mc < 0) mc = 0;                                                      \
        if (mc > N2 - 1) mc = N2 - 1;                                            \
        const int idx = (BCUR) * N2 + t;                                         \
        int4 c4 = make_int4(-1, -1, -1, -1);                                     \
        float fv = NEGV;                                                         \
        if (t < N2) {                                                            \
            c4 = __ldcs(reinterpret_cast<const int4*>(cap) + idx);               \
            const float lg = __ldcs(logits + idx);                               \
            if (__ldcs(legal + idx)) fv = lg;                                    \
        }                                                                        \
        int h_nxt = 0, sg_nxt = 0;                                               \
        if ((BNXT) < B) {                                                        \
            if (t < N2) h_nxt = __ldcs(hist + (BNXT) * N2 + t);                  \
            if (w11)    sg_nxt = __ldcs(sgi + (BNXT) * 32 + l);                  \
        }                                                                        \
        /* phase 1: clears + group XOR + pass-1 insert */                        \
        if (CLI) {                                                               \
            sh_tab[P][CL1] = -1; sh_tab[P][CL2] = -1;                            \
        }                                                                        \
        if (t == 0) sh_ovfn[P] = 0;                                              \
        if (w11) {                                                               \
            int si = sg_cur;                                                     \
            si = si < 0 ? 0 : (si >= N2 ? N2 - 1 : si);                          \
            int d = sh_zd[1 - pl][si];                                           \
            d ^= __shfl_xor_sync(0xffffffffu, d, 1);                             \
            d ^= __shfl_xor_sync(0xffffffffu, d, 2);                             \
            if ((l & 3) == 0) sh_gx[P][l >> 2] = d;                              \
        }                                                                        \
        const bool ins = (t < mc);    /* sentinel handled at probe */            \
        int key = 0; unsigned hsh = 0; int s1 = 0, s2 = 0;                       \
        if (ins) {                                                               \
            key = h_cur;                                                         \
            hsh = (unsigned)key * 2654435761u;                                   \
            s1 = (int)(hsh >> 22);                                               \
            s2 = (int)((hsh >> 12) & (TS - 1));                                  \
            sh_tab[P][s1] = key;                                                 \
        }                                                                        \
        __syncthreads();                                                         \
        /* phase 2: readback -> CAS s2 -> overflow */                            \
        if (ins && sh_tab[P][s1] != key) {                                       \
            int prev = atomicCAS(&sh_tab[P][s2], -1, key);                       \
            if (prev != -1 && prev != key) {                                     \
                const int oi = atomicAdd(&sh_ovfn[P], 1);                        \
                if (oi < OVF) sh_ovf[P][oi] = key;                               \
            }                                                                    \
        }                                                                        \
        __syncthreads();                                                         \
        /* phase 3: candidate + membership + output */                           \
        if (t < N2) {                                                            \
            int cd = 0;                                                          \
            if (c4.x >= 0) cd ^= sh_gx[P][c4.x & 7];                             \
            if (c4.y >= 0) cd ^= sh_gx[P][c4.y & 7];                             \
            if (c4.z >= 0) cd ^= sh_gx[P][c4.z & 7];                             \
            if (c4.w >= 0) cd ^= sh_gx[P][c4.w & 7];                             \
            const int cand = ch ^ sh_zd[pl][t] ^ cd;                             \
            const unsigned hh = (unsigned)cand * 2654435761u;                    \
            bool rep = (sh_tab[P][hh >> 22] == cand) |                           \
                       (sh_tab[P][(hh >> 12) & (TS - 1)] == cand) |              \
                       (cand == I32MIN_V);  /* sentinel: mc < M always */        \
            int ovn = sh_ovfn[P];                                                \
            const bool fbk = (ovn > OVF);                                        \
            if (ovn > OVF) ovn = OVF;                                            \
            for (int i2 = 0; i2 < ovn; ++i2) rep |= (sh_ovf[P][i2] == cand);     \
            if (fbk && !rep) {                                                   \
                for (int q = 0; q < mc && !rep; ++q)                             \
                    rep = (hist[(BCUR) * N2 + q] == cand);                       \
            }                                                                    \
            __stcs(out + idx, rep ? NEGV : fv);                                  \
        }                                                                        \
        CLI = ins; CL1 = s1; CL2 = s2;                                           \
        h_cur = h_nxt; sg_cur = sg_nxt;                                          \
    }

    for (int b = blockIdx.x; b < B; b += 2 * g) {
        BODY(0, b, b + g, cl_ins0, cl0_1, cl0_2)
        const int b1 = b + g;
        if (b1 < B) {
            BODY(1, b1, b1 + g, cl_ins1, cl1_1, cl1_2)
        }
    }
#undef BODY
}

extern "C" void kernel_launch(void* const* d_in, const int* in_sizes, int n_in,
                              void* d_out, int out_size)
{
    const float* logits = (const float*)d_in[0];
    const int*   legal  = (const int*)d_in[1];
    const int*   player = (const int*)d_in[2];
    const int*   chash  = (const int*)d_in[3];
    const int*   hist   = (const int*)d_in[4];
    const int*   mcnt   = (const int*)d_in[5];
    const int*   zpos   = (const int*)d_in[6];
    const int*   sgi    = (const int*)d_in[7];
    const int*   cap    = (const int*)d_in[10];
    float*       out    = (float*)d_out;

    const int B = in_sizes[2];           // current_player: B elements

    board_kernel<<<GRIDB, NTHR>>>(logits, legal, player, chash, hist, mcnt,
                                  zpos, sgi, cap, out, B);
}

// round 17
// speedup vs baseline: 3.9652x; 2.5973x over previous
#include <cuda_runtime.h>
#include <cstdint>

#define N2    361
#define NTHR  384
#define TS    1024
#define OVF   16
#define NEGV  (-1000000000.0f)
#define I32MIN_V (-2147483647 - 1)
#define GRIDB 740                     // 148 SMs * 5 resident blocks

__global__ __launch_bounds__(NTHR, 5)
void board_kernel(const float* __restrict__ logits,
                  const int* __restrict__ legal,      // bool as int32
                  const int* __restrict__ player,
                  const int* __restrict__ cur_hash,
                  const int* __restrict__ hist,
                  const int* __restrict__ move_count,
                  const int* __restrict__ ZposT,
                  const int* __restrict__ sgi,
                  const int* __restrict__ cap,
                  float* __restrict__ out,
                  int B)
{
    __shared__ int sh_tab[2][TS];     // double-buffered exact table
    __shared__ int sh_gx[2][8];
    __shared__ int sh_ovf[2][OVF];
    __shared__ int sh_ovfn[2];
    __shared__ int sh_zd[2][N2];      // delta tables: [0]=ze^zb, [1]=ze^zw

    const int t = threadIdx.x;
    const bool w11 = ((t >> 5) == 11);
    const int l = t & 31;

    for (int i = t; i < N2; i += NTHR) {
        const int ze = ZposT[i];
        sh_zd[0][i] = ze ^ ZposT[N2 + i];
        sh_zd[1][i] = ze ^ ZposT[2 * N2 + i];
    }
    for (int i = t; i < 2 * TS / 4; i += NTHR)
        reinterpret_cast<int4*>(sh_tab)[i] = make_int4(-1, -1, -1, -1);
    if (t < 2) sh_ovfn[t] = 0;
    __syncthreads();

    // per-buffer clear state (slots written 2 boards ago)
    bool cl_ins0 = false, cl_ins1 = false;
    int  cl0_1 = 0, cl0_2 = 0, cl0_3 = 0;
    int  cl1_1 = 0, cl1_2 = 0, cl1_3 = 0;

    const int g = gridDim.x;

    // prologue prefetch for first board
    int h_cur = 0, sg_cur = 0;
    {
        const int b0 = blockIdx.x;
        if (b0 < B) {
            if (t < N2) h_cur = __ldcs(hist + b0 * N2 + t);
            if (w11)    sg_cur = __ldcs(sgi + b0 * 32 + l);
        }
    }

#define BODY(P, BCUR, BNXT, CLI, CL1, CL2, CL3)                                  \
    {                                                                            \
        const int pl = player[BCUR] & 1;                                         \
        const int ch = cur_hash[BCUR];                                           \
        int mc = move_count[BCUR];                                               \
        if (mc < 0) mc = 0;                                                      \
        if (mc > N2 - 1) mc = N2 - 1;                                            \
        const int idx = (BCUR) * N2 + t;                                         \
        int4 c4 = make_int4(-1, -1, -1, -1);                                     \
        float lg = 0.0f; int lgl = 0;                                            \
        if (t < N2) {                                                            \
            c4  = __ldcs(reinterpret_cast<const int4*>(cap) + idx);              \
            lg  = __ldcs(logits + idx);                                          \
            lgl = __ldcs(legal + idx);                                           \
        }                                                                        \
        int h_nxt = 0, sg_nxt = 0;                                               \
        if ((BNXT) < B) {                                                        \
            if (t < N2) h_nxt = __ldcs(hist + (BNXT) * N2 + t);                  \
            if (w11)    sg_nxt = __ldcs(sgi + (BNXT) * 32 + l);                  \
        }                                                                        \
        /* phase 1: clears + group XOR + pass-1 insert */                        \
        if (CLI) {                                                               \
            sh_tab[P][CL1] = -1; sh_tab[P][CL2] = -1; sh_tab[P][CL3] = -1;       \
        }                                                                        \
        if (t == 0) sh_ovfn[P] = 0;                                              \
        if (w11) {                                                               \
            int si = sg_cur;                                                     \
            si = si < 0 ? 0 : (si >= N2 ? N2 - 1 : si);                          \
            int d = sh_zd[1 - pl][si];                                           \
            d ^= __shfl_xor_sync(0xffffffffu, d, 1);                             \
            d ^= __shfl_xor_sync(0xffffffffu, d, 2);                             \
            if ((l & 3) == 0) sh_gx[P][l >> 2] = d;                              \
        }                                                                        \
        const bool ins = (t < mc);    /* sentinel handled at probe */            \
        int key = 0; unsigned hsh = 0; int s1 = 0, s2 = 0, s3 = 0;               \
        if (ins) {                                                               \
            key = h_cur;                                                         \
            hsh = (unsigned)key * 2654435761u;                                   \
            s1 = (int)(hsh >> 22);                                               \
            s2 = (int)((hsh >> 12) & (TS - 1));                                  \
            s3 = (int)((hsh ^ (hsh >> 9)) & (TS - 1));                           \
            sh_tab[P][s1] = key;                                                 \
        }                                                                        \
        __syncthreads();                                                         \
        /* phase 2: readback -> CAS s2 -> CAS s3 -> overflow */                  \
        if (ins && sh_tab[P][s1] != key) {                                       \
            int prev = atomicCAS(&sh_tab[P][s2], -1, key);                       \
            if (prev != -1 && prev != key) {                                     \
                prev = atomicCAS(&sh_tab[P][s3], -1, key);                       \
                if (prev != -1 && prev != key) {                                 \
                    const int oi = atomicAdd(&sh_ovfn[P], 1);                    \
                    if (oi < OVF) sh_ovf[P][oi] = key;                           \
                }                                                                \
            }                                                                    \
        }                                                                        \
        __syncthreads();                                                         \
        /* phase 3: candidate + membership + output */                           \
        if (t < N2) {                                                            \
            int cd = 0;                                                          \
            if (c4.x >= 0) cd ^= sh_gx[P][c4.x & 7];                             \
            if (c4.y >= 0) cd ^= sh_gx[P][c4.y & 7];                             \
            if (c4.z >= 0) cd ^= sh_gx[P][c4.z & 7];                             \
            if (c4.w >= 0) cd ^= sh_gx[P][c4.w & 7];                             \
            const int cand = ch ^ sh_zd[pl][t] ^ cd;                             \
            const unsigned hh = (unsigned)cand * 2654435761u;                    \
            bool rep = (sh_tab[P][hh >> 22] == cand) |                           \
                       (sh_tab[P][(hh >> 12) & (TS - 1)] == cand) |              \
                       (sh_tab[P][(hh ^ (hh >> 9)) & (TS - 1)] == cand) |        \
                       (cand == I32MIN_V);  /* sentinel: mc < M always */        \
            int ovn = sh_ovfn[P];                                                \
            const bool fbk = (ovn > OVF);                                        \
            if (ovn > OVF) ovn = OVF;                                            \
            for (int i2 = 0; i2 < ovn; ++i2) rep |= (sh_ovf[P][i2] == cand);     \
            if (fbk && !rep) {                                                   \
                for (int q = 0; q < mc && !rep; ++q)                             \
                    rep = (hist[(BCUR) * N2 + q] == cand);                       \
            }                                                                    \
            __stcs(out + idx, ((lgl != 0) & !rep) ? lg : NEGV);                  \
        }                                                                        \
        CLI = ins; CL1 = s1; CL2 = s2; CL3 = s3;                                 \
        h_cur = h_nxt; sg_cur = sg_nxt;                                          \
    }

    for (int b = blockIdx.x; b < B; b += 2 * g) {
        BODY(0, b, b + g, cl_ins0, cl0_1, cl0_2, cl0_3)
        const int b1 = b + g;
        if (b1 < B) {
            BODY(1, b1, b1 + g, cl_ins1, cl1_1, cl1_2, cl1_3)
        }
    }
#undef BODY
}

extern "C" void kernel_launch(void* const* d_in, const int* in_sizes, int n_in,
                              void* d_out, int out_size)
{
    const float* logits = (const float*)d_in[0];
    const int*   legal  = (const int*)d_in[1];
    const int*   player = (const int*)d_in[2];
    const int*   chash  = (const int*)d_in[3];
    const int*   hist   = (const int*)d_in[4];
    const int*   mcnt   = (const int*)d_in[5];
    const int*   zpos   = (const int*)d_in[6];
    const int*   sgi    = (const int*)d_in[7];
    const int*   cap    = (const int*)d_in[10];
    float*       out    = (float*)d_out;

    const int B = in_sizes[2];           // current_player: B elements

    board_kernel<<<GRIDB, NTHR>>>(logits, legal, player, chash, hist, mcnt,
                                  zpos, sgi, cap, out, B);
}